// round 7
// baseline (speedup 1.0000x reference)
#include <cuda_runtime.h>
#include <math.h>

#define FEAT 2048
#define NOUT 40        // 20 cls cols + 20 flow cols
#define MT   128       // rows per CTA
#define KT   64        // k per smem tile
#define XST  132       // padded row stride (floats) for transposed x tile

// ---------------- device scratch (no allocations allowed) ----------------
__device__ float g_WcPart[8 * 2048 * 40];   // K1 partials [ks][2048][40]
__device__ float g_Wc[2048 * 40];           // combined weights [j][40]
__device__ float g_bias[40];                // combined bias
__device__ float g_HPart[2u * 16384 * 40];  // K2 partials [ks][B][40]

// ---------------- f32x2 helpers ----------------
__device__ __forceinline__ unsigned long long fma2(unsigned long long a,
                                                   unsigned long long b,
                                                   unsigned long long c) {
    unsigned long long d;
    asm("fma.rn.f32x2 %0, %1, %2, %3;" : "=l"(d) : "l"(a), "l"(b), "l"(c));
    return d;
}
__device__ __forceinline__ unsigned long long pk2(float x, float y) {
    unsigned long long d;
    asm("mov.b64 %0, {%1, %2};" : "=l"(d) : "f"(x), "f"(y));
    return d;
}

// ---------------- tall-skinny GEMM: C[M,40] = X[M,2048] @ W[2048,40] ----------------
// MODE 0: W read from g_Wc, partials -> g_HPart   (main pass over x)
// MODE 1: W gathered from (Wa=W_cls, Wb=W_fl), partials -> g_WcPart (weight combine)
// Block: 128 threads = 4 warps: cg = warp&1 owns 20 output cols, rh = warp>>1 owns 64 rows.
// Each lane owns 2 rows (rowA, rowA+1) x 10 column-pairs -> 20 FFMA2 per k.
template <int MODE>
__global__ __launch_bounds__(128)
void gemm40(const float* __restrict__ X, int M,
            const float* __restrict__ Wa, const float* __restrict__ Wb,
            int kRange) {
    __shared__ float xs[KT * XST];   // xs[k][row], transposed tile
    __shared__ float ws[KT * NOUT];  // ws[k][n]

    const int t    = threadIdx.x;
    const int lane = t & 31;
    const int warp = t >> 5;
    const int cg   = warp & 1;
    const int rh   = warp >> 1;
    const int rowA = rh * 64 + 2 * lane;      // 0..126, even
    const int m0   = blockIdx.x * MT;
    const int ks   = blockIdx.y;
    const int k0b  = ks * kRange;

    unsigned long long acc[2][10];
#pragma unroll
    for (int r = 0; r < 2; r++)
#pragma unroll
        for (int q = 0; q < 10; q++) acc[r][q] = 0ull;

    for (int kb = 0; kb < kRange; kb += KT) {
        const int k0 = k0b + kb;

        // stage X tile (coalesced float4 LDG, transposed STS, pad->2-way)
#pragma unroll
        for (int i = 0; i < 16; i++) {
            int idx = t + i * 128;                 // 0..2047
            int f4 = idx & 15, row = idx >> 4;     // 16 float4 cols x 128 rows
            float4 v = *reinterpret_cast<const float4*>(
                X + (size_t)(m0 + row) * FEAT + k0 + f4 * 4);
            xs[(4 * f4 + 0) * XST + row] = v.x;
            xs[(4 * f4 + 1) * XST + row] = v.y;
            xs[(4 * f4 + 2) * XST + row] = v.z;
            xs[(4 * f4 + 3) * XST + row] = v.w;
        }
        // stage W tile
        if (MODE == 0) {
#pragma unroll
            for (int i = 0; i < 5; i++) {
                int idx = t + i * 128;             // 0..639 float4s (contiguous rows)
                reinterpret_cast<float4*>(ws)[idx] =
                    reinterpret_cast<const float4*>(g_Wc)[(size_t)k0 * 10 + idx];
            }
        } else {
#pragma unroll
            for (int i = 0; i < 20; i++) {
                int idx = t + i * 128;             // 0..2559
                int k = idx / 40, n = idx % 40;
                float v = (n < 20) ? Wa[(size_t)(k0 + k) * 20 + n]
                                   : Wb[(size_t)(k0 + k) * 20 + (n - 20)];
                ws[k * NOUT + n] = v;
            }
        }
        __syncthreads();

#pragma unroll 4
        for (int kk = 0; kk < KT; kk++) {
            float2 xv = *reinterpret_cast<const float2*>(xs + kk * XST + rowA);
            unsigned long long x0 = pk2(xv.x, xv.x);
            unsigned long long x1 = pk2(xv.y, xv.y);
            const float4* wr =
                reinterpret_cast<const float4*>(ws + kk * NOUT + cg * 20);
#pragma unroll
            for (int u = 0; u < 5; u++) {
                float4 wv = wr[u];                         // broadcast LDS.128
                unsigned long long wa = pk2(wv.x, wv.y);
                unsigned long long wb2 = pk2(wv.z, wv.w);
                acc[0][2 * u]     = fma2(x0, wa,  acc[0][2 * u]);
                acc[0][2 * u + 1] = fma2(x0, wb2, acc[0][2 * u + 1]);
                acc[1][2 * u]     = fma2(x1, wa,  acc[1][2 * u]);
                acc[1][2 * u + 1] = fma2(x1, wb2, acc[1][2 * u + 1]);
            }
        }
        __syncthreads();
    }

    float* outBase = (MODE == 0) ? g_HPart : g_WcPart;
#pragma unroll
    for (int r = 0; r < 2; r++) {
        float* dst = outBase + ((size_t)ks * M + m0 + rowA + r) * NOUT + cg * 20;
#pragma unroll
        for (int q = 0; q < 10; q++)
            *reinterpret_cast<unsigned long long*>(dst + 2 * q) = acc[r][q];
    }
}

// ---------------- reduce K1 partials -> g_Wc, and compute combined bias ----------------
__global__ void k1_reduce(const float* __restrict__ b_enc,
                          const float* __restrict__ Wcls,
                          const float* __restrict__ bcls,
                          const float* __restrict__ Wfl,
                          const float* __restrict__ bfl) {
    if (blockIdx.x < 320) {
        int idx = blockIdx.x * 256 + threadIdx.x;  // 0..81919
        float s = 0.f;
#pragma unroll
        for (int ksp = 0; ksp < 8; ksp++) s += g_WcPart[ksp * 81920 + idx];
        g_Wc[idx] = s;
    } else {
        // bias[n] = b_enc . W_head[:,n] + b_head[n]; 8 warps x 5 rounds = 40 cols
        int w = threadIdx.x >> 5, lane = threadIdx.x & 31;
        for (int r = 0; r < 5; r++) {
            int n = w * 5 + r;
            float s = 0.f;
            for (int k = lane; k < FEAT; k += 32)
                s += b_enc[k] * ((n < 20) ? Wcls[k * 20 + n] : Wfl[k * 20 + (n - 20)]);
#pragma unroll
            for (int off = 16; off; off >>= 1)
                s += __shfl_down_sync(0xffffffffu, s, off);
            if (lane == 0)
                g_bias[n] = s + ((n < 20) ? bcls[n] : bfl[n - 20]);
        }
    }
}

// ---------------- fused epilogue: add partials+bias, softmax both heads, threshold ----
__global__ void epilogue40(float* __restrict__ out, int M) {
    int row = blockIdx.x * 256 + threadIdx.x;
    if (row >= M) return;
    float l[40];
    const float4* p0 = reinterpret_cast<const float4*>(g_HPart + (size_t)row * 40);
    const float4* p1 = reinterpret_cast<const float4*>(g_HPart + ((size_t)M + row) * 40);
    const float4* bb = reinterpret_cast<const float4*>(g_bias);
#pragma unroll
    for (int u = 0; u < 10; u++) {
        float4 a = p0[u], b = p1[u], c = bb[u];
        l[4 * u + 0] = a.x + b.x + c.x;
        l[4 * u + 1] = a.y + b.y + c.y;
        l[4 * u + 2] = a.z + b.z + c.z;
        l[4 * u + 3] = a.w + b.w + c.w;
    }
    // cls softmax
    float m = l[0];
#pragma unroll
    for (int n = 1; n < 20; n++) m = fmaxf(m, l[n]);
    float e[20];
    float s = 0.f;
#pragma unroll
    for (int n = 0; n < 20; n++) { e[n] = expf(l[n] - m); s += e[n]; }
    // flow softmax -> tau = min prob
    float mf = l[20];
#pragma unroll
    for (int n = 21; n < 40; n++) mf = fmaxf(mf, l[n]);
    float sf = 0.f, mn = 1e30f;
#pragma unroll
    for (int n = 20; n < 40; n++) {
        float ef = expf(l[n] - mf);
        sf += ef;
        mn = fminf(mn, ef);
    }
    float inv  = 1.f / s;
    float pred = inv;          // exp(0)/s at the max logit
    float tau  = mn / sf;
    float scale = (pred >= tau + 0.31f) ? inv : 0.f;

    float4* o = reinterpret_cast<float4*>(out + (size_t)row * 20);
#pragma unroll
    for (int u = 0; u < 5; u++)
        o[u] = make_float4(e[4 * u + 0] * scale, e[4 * u + 1] * scale,
                           e[4 * u + 2] * scale, e[4 * u + 3] * scale);
}

// ---------------- launcher ----------------
extern "C" void kernel_launch(void* const* d_in, const int* in_sizes, int n_in,
                              void* d_out, int out_size) {
    const float* x    = (const float*)d_in[0];
    const float* Wenc = (const float*)d_in[1];
    const float* benc = (const float*)d_in[2];
    const float* Wcls = (const float*)d_in[3];
    const float* bcls = (const float*)d_in[4];
    const float* Wfl  = (const float*)d_in[5];
    const float* bfl  = (const float*)d_in[6];
    float* out = (float*)d_out;
    const int Bsz = in_sizes[0] / FEAT;   // 16384

    // K1: Wc partials = W_enc[2048,2048] @ [W_cls|W_fl]   (8-way K split)
    gemm40<1><<<dim3(2048 / MT, 8), 128>>>(Wenc, 2048, Wcls, Wfl, FEAT / 8);
    // K1R: reduce partials -> g_Wc; compute combined bias
    k1_reduce<<<321, 256>>>(benc, Wcls, bcls, Wfl, bfl);
    // K2: H partials = x[B,2048] @ g_Wc[2048,40]          (2-way K split)
    gemm40<0><<<dim3(Bsz / MT, 2), 128>>>(x, Bsz, nullptr, nullptr, FEAT / 2);
    // K2R: reduce + bias + dual softmax + confidence threshold -> out
    epilogue40<<<(Bsz + 255) / 256, 256>>>(out, Bsz);
}

// round 8
// speedup vs baseline: 1.0100x; 1.0100x over previous
#include <cuda_runtime.h>
#include <math.h>

#define FEAT 2048
#define NOUT 40        // 20 cls cols + 20 flow cols
#define MT   128       // rows per CTA
#define KT   64        // k per smem tile
#define XST  132       // padded row stride (floats) for transposed x tile

// ---------------- device scratch (no allocations allowed) ----------------
__device__ float g_WcPart[8 * 2048 * 40];   // K1 partials [ks][2048][40]
__device__ float g_Wc[2048 * 40];           // combined weights [j][40]
__device__ float g_bias[40];                // combined bias
__device__ float g_HPart[2u * 16384 * 40];  // K2 partials [ks][B][40]

// ---------------- f32x2 helpers ----------------
__device__ __forceinline__ unsigned long long fma2(unsigned long long a,
                                                   unsigned long long b,
                                                   unsigned long long c) {
    unsigned long long d;
    asm("fma.rn.f32x2 %0, %1, %2, %3;" : "=l"(d) : "l"(a), "l"(b), "l"(c));
    return d;
}
__device__ __forceinline__ unsigned long long pk2(float x, float y) {
    unsigned long long d;
    asm("mov.b64 %0, {%1, %2};" : "=l"(d) : "f"(x), "f"(y));
    return d;
}

// ---------------- tall-skinny GEMM: C[M,40] = X[M,2048] @ W[2048,40] ----------------
// MODE 0: W read from g_Wc, partials -> g_HPart   (main pass over x)
// MODE 1: W gathered from (Wa=W_cls, Wb=W_fl), partials -> g_WcPart (weight combine)
// Block: 128 threads = 4 warps: cg = warp&1 owns 20 output cols, rh = warp>>1 owns 64 rows.
// Each lane owns 2 rows (rowA, rowA+1) x 10 column-pairs -> 20 FFMA2 per k.
template <int MODE>
__global__ __launch_bounds__(128)
void gemm40(const float* __restrict__ X, int M,
            const float* __restrict__ Wa, const float* __restrict__ Wb,
            int kRange) {
    __shared__ float xs[KT * XST];   // xs[k][row], transposed tile
    __shared__ float ws[KT * NOUT];  // ws[k][n]

    const int t    = threadIdx.x;
    const int lane = t & 31;
    const int warp = t >> 5;
    const int cg   = warp & 1;
    const int rh   = warp >> 1;
    const int rowA = rh * 64 + 2 * lane;      // 0..126, even
    const int m0   = blockIdx.x * MT;
    const int ks   = blockIdx.y;
    const int k0b  = ks * kRange;

    unsigned long long acc[2][10];
#pragma unroll
    for (int r = 0; r < 2; r++)
#pragma unroll
        for (int q = 0; q < 10; q++) acc[r][q] = 0ull;

    for (int kb = 0; kb < kRange; kb += KT) {
        const int k0 = k0b + kb;

        // stage X tile (coalesced float4 LDG, transposed STS, pad->2-way)
#pragma unroll
        for (int i = 0; i < 16; i++) {
            int idx = t + i * 128;                 // 0..2047
            int f4 = idx & 15, row = idx >> 4;     // 16 float4 cols x 128 rows
            float4 v = *reinterpret_cast<const float4*>(
                X + (size_t)(m0 + row) * FEAT + k0 + f4 * 4);
            xs[(4 * f4 + 0) * XST + row] = v.x;
            xs[(4 * f4 + 1) * XST + row] = v.y;
            xs[(4 * f4 + 2) * XST + row] = v.z;
            xs[(4 * f4 + 3) * XST + row] = v.w;
        }
        // stage W tile
        if (MODE == 0) {
#pragma unroll
            for (int i = 0; i < 5; i++) {
                int idx = t + i * 128;             // 0..639 float4s (contiguous rows)
                reinterpret_cast<float4*>(ws)[idx] =
                    reinterpret_cast<const float4*>(g_Wc)[(size_t)k0 * 10 + idx];
            }
        } else {
#pragma unroll
            for (int i = 0; i < 20; i++) {
                int idx = t + i * 128;             // 0..2559
                int k = idx / 40, n = idx % 40;
                float v = (n < 20) ? Wa[(size_t)(k0 + k) * 20 + n]
                                   : Wb[(size_t)(k0 + k) * 20 + (n - 20)];
                ws[k * NOUT + n] = v;
            }
        }
        __syncthreads();

#pragma unroll 4
        for (int kk = 0; kk < KT; kk++) {
            float2 xv = *reinterpret_cast<const float2*>(xs + kk * XST + rowA);
            unsigned long long x0 = pk2(xv.x, xv.x);
            unsigned long long x1 = pk2(xv.y, xv.y);
            const float4* wr =
                reinterpret_cast<const float4*>(ws + kk * NOUT + cg * 20);
#pragma unroll
            for (int u = 0; u < 5; u++) {
                float4 wv = wr[u];                         // broadcast LDS.128
                unsigned long long wa = pk2(wv.x, wv.y);
                unsigned long long wb2 = pk2(wv.z, wv.w);
                acc[0][2 * u]     = fma2(x0, wa,  acc[0][2 * u]);
                acc[0][2 * u + 1] = fma2(x0, wb2, acc[0][2 * u + 1]);
                acc[1][2 * u]     = fma2(x1, wa,  acc[1][2 * u]);
                acc[1][2 * u + 1] = fma2(x1, wb2, acc[1][2 * u + 1]);
            }
        }
        __syncthreads();
    }

    float* outBase = (MODE == 0) ? g_HPart : g_WcPart;
#pragma unroll
    for (int r = 0; r < 2; r++) {
        float* dst = outBase + ((size_t)ks * M + m0 + rowA + r) * NOUT + cg * 20;
#pragma unroll
        for (int q = 0; q < 10; q++)
            *reinterpret_cast<unsigned long long*>(dst + 2 * q) = acc[r][q];
    }
}

// ---------------- reduce K1 partials -> g_Wc, and compute combined bias ----------------
__global__ void k1_reduce(const float* __restrict__ b_enc,
                          const float* __restrict__ Wcls,
                          const float* __restrict__ bcls,
                          const float* __restrict__ Wfl,
                          const float* __restrict__ bfl) {
    if (blockIdx.x < 320) {
        int idx = blockIdx.x * 256 + threadIdx.x;  // 0..81919
        float s = 0.f;
#pragma unroll
        for (int ksp = 0; ksp < 8; ksp++) s += g_WcPart[ksp * 81920 + idx];
        g_Wc[idx] = s;
    } else {
        // bias[n] = b_enc . W_head[:,n] + b_head[n]; 8 warps x 5 rounds = 40 cols
        int w = threadIdx.x >> 5, lane = threadIdx.x & 31;
        for (int r = 0; r < 5; r++) {
            int n = w * 5 + r;
            float s = 0.f;
            for (int k = lane; k < FEAT; k += 32)
                s += b_enc[k] * ((n < 20) ? Wcls[k * 20 + n] : Wfl[k * 20 + (n - 20)]);
#pragma unroll
            for (int off = 16; off; off >>= 1)
                s += __shfl_down_sync(0xffffffffu, s, off);
            if (lane == 0)
                g_bias[n] = s + ((n < 20) ? bcls[n] : bfl[n - 20]);
        }
    }
}

// ---------------- fused epilogue: add partials+bias, softmax both heads, threshold ----
__global__ void epilogue40(float* __restrict__ out, int M) {
    int row = blockIdx.x * 256 + threadIdx.x;
    if (row >= M) return;
    float l[40];
    const float4* p0 = reinterpret_cast<const float4*>(g_HPart + (size_t)row * 40);
    const float4* p1 = reinterpret_cast<const float4*>(g_HPart + ((size_t)M + row) * 40);
    const float4* bb = reinterpret_cast<const float4*>(g_bias);
#pragma unroll
    for (int u = 0; u < 10; u++) {
        float4 a = p0[u], b = p1[u], c = bb[u];
        l[4 * u + 0] = a.x + b.x + c.x;
        l[4 * u + 1] = a.y + b.y + c.y;
        l[4 * u + 2] = a.z + b.z + c.z;
        l[4 * u + 3] = a.w + b.w + c.w;
    }
    // cls softmax
    float m = l[0];
#pragma unroll
    for (int n = 1; n < 20; n++) m = fmaxf(m, l[n]);
    float e[20];
    float s = 0.f;
#pragma unroll
    for (int n = 0; n < 20; n++) { e[n] = expf(l[n] - m); s += e[n]; }
    // flow softmax -> tau = min prob
    float mf = l[20];
#pragma unroll
    for (int n = 21; n < 40; n++) mf = fmaxf(mf, l[n]);
    float sf = 0.f, mn = 1e30f;
#pragma unroll
    for (int n = 20; n < 40; n++) {
        float ef = expf(l[n] - mf);
        sf += ef;
        mn = fminf(mn, ef);
    }
    float inv  = 1.f / s;
    float pred = inv;          // exp(0)/s at the max logit
    float tau  = mn / sf;
    float scale = (pred >= tau + 0.31f) ? inv : 0.f;

    float4* o = reinterpret_cast<float4*>(out + (size_t)row * 20);
#pragma unroll
    for (int u = 0; u < 5; u++)
        o[u] = make_float4(e[4 * u + 0] * scale, e[4 * u + 1] * scale,
                           e[4 * u + 2] * scale, e[4 * u + 3] * scale);
}

// ---------------- launcher ----------------
extern "C" void kernel_launch(void* const* d_in, const int* in_sizes, int n_in,
                              void* d_out, int out_size) {
    const float* x    = (const float*)d_in[0];
    const float* Wenc = (const float*)d_in[1];
    const float* benc = (const float*)d_in[2];
    const float* Wcls = (const float*)d_in[3];
    const float* bcls = (const float*)d_in[4];
    const float* Wfl  = (const float*)d_in[5];
    const float* bfl  = (const float*)d_in[6];
    float* out = (float*)d_out;
    const int Bsz = in_sizes[0] / FEAT;   // 16384

    // K1: Wc partials = W_enc[2048,2048] @ [W_cls|W_fl]   (8-way K split)
    gemm40<1><<<dim3(2048 / MT, 8), 128>>>(Wenc, 2048, Wcls, Wfl, FEAT / 8);
    // K1R: reduce partials -> g_Wc; compute combined bias
    k1_reduce<<<321, 256>>>(benc, Wcls, bcls, Wfl, bfl);
    // K2: H partials = x[B,2048] @ g_Wc[2048,40]          (2-way K split)
    gemm40<0><<<dim3(Bsz / MT, 2), 128>>>(x, Bsz, nullptr, nullptr, FEAT / 2);
    // K2R: reduce + bias + dual softmax + confidence threshold -> out
    epilogue40<<<(Bsz + 255) / 256, 256>>>(out, Bsz);
}